// round 9
// baseline (speedup 1.0000x reference)
#include <cuda_runtime.h>
#include <cstdint>

#define BB    2048
#define TT    1024
#define NW    8          // warps per CTA
#define GRIDX 740        // 5 CTAs/SM * 148 SMs: exactly one wave
#define CPR   8          // chunks per row per warp (16 rows each)

__device__ __forceinline__ uint32_t s2u(const void* p) {
    return (uint32_t)__cvta_generic_to_shared(p);
}

// ============================ Fused decoder ================================
// Persistent single-wave grid: CTA bx processes rows bx, bx+740, bx+1480.
// Each warp owns 128 consecutive z rows of the current batch row, streamed
// through a private 2-slot cp.async ring (2KB XOR-swizzled chunks). The chunk
// pipeline crosses the row boundary (stages 6,7 issue next row's stages 0,1)
// using uniform per-row base pointers -> no dynamic address math, no drain.
__global__ __launch_bounds__(256, 5)
void fused_decoder_kernel(const float* __restrict__ init_states,
                          const float* __restrict__ z,
                          const float* __restrict__ W,
                          float* __restrict__ out) {
    __shared__ alignas(16) float4 zring[NW][2][128];  // 32KB per-warp rings
    __shared__ alignas(16) float2 sv[TT];             // 8KB per-timestep vectors
    __shared__ float2 agg[8];
    __shared__ float  sPW[5][4];
    __shared__ float4 sW0[8], sW1[8];

    const int bx   = blockIdx.x;
    const int tid  = threadIdx.x;
    const int lane = tid & 31;
    const int warp = tid >> 5;
    const int nrows = (BB - bx + GRIDX - 1) / GRIDX;  // 2 or 3

    if (tid < 64) {
        const int rr = tid >> 5, c = tid & 31;
        reinterpret_cast<float*>(rr ? sW1 : sW0)[c] = W[rr * 34 + 2 + c];
    }

    // ---- precomputed swizzled offsets (lane-only) ----
    int woff[4], roff[4];
    #pragma unroll
    for (int k = 0; k < 4; ++k) {
        const int i2 = lane + 32 * k;
        const int row = i2 >> 3, j = i2 & 7;
        woff[k] = row * 8 + ((j + row) & 7);
    }
    const int rrow = lane >> 1;
    const int half = (lane & 1) * 4;
    #pragma unroll
    for (int k = 0; k < 4; ++k) {
        const int c = half + k;
        roff[k] = rrow * 8 + ((c + rrow) & 7);
    }

    const float4* z4 = reinterpret_cast<const float4*>(z);
    const uint32_t slotu[2] = { s2u(&zring[warp][0][0]), s2u(&zring[warp][1][0]) };

    auto rowbase = [&](int r) {
        return z4 + ((size_t)(bx + r * GRIDX) * TT + warp * 128) * 8;
    };
    auto issue = [&](const float4* base, int st, int par) {
        const float4* src = base + st * 128 + lane;
        const uint32_t dst = slotu[par];
        #pragma unroll
        for (int k = 0; k < 4; ++k) {
            asm volatile("cp.async.cg.shared.global [%0], [%1], 16;"
                         :: "r"(dst + (uint32_t)woff[k] * 16u), "l"(src + 32 * k));
        }
    };

    const float4* cur = rowbase(0);
    issue(cur, 0, 0);
    asm volatile("cp.async.commit_group;" ::: "memory");
    issue(cur, 1, 1);
    asm volatile("cp.async.commit_group;" ::: "memory");

    __syncthreads();                           // publish sW0/sW1

    const float a00 = __ldg(&W[0]),  a01 = __ldg(&W[1]);
    const float a10 = __ldg(&W[34]), a11 = __ldg(&W[35]);

    for (int r = 0; r < nrows; ++r) {
        const int b = bx + r * GRIDX;
        const float4* nxt = (r + 1 < nrows) ? rowbase(r + 1) : nullptr;

        // ---------------- Phase A: 8 pipelined chunks ----------------
        #pragma unroll 1
        for (int s = 0; s < CPR; ++s) {
            asm volatile("cp.async.wait_group 1;" ::: "memory");
            __syncwarp();
            const int par = (r * CPR + s) & 1;
            const float4* slot = &zring[warp][par][0];

            float px = 0.f, py = 0.f;
            #pragma unroll
            for (int k = 0; k < 4; ++k) {
                const float4 q  = slot[roff[k]];
                const float4 w0 = sW0[half + k];
                const float4 w1 = sW1[half + k];
                px = fmaf(q.x, w0.x, fmaf(q.y, w0.y, fmaf(q.z, w0.z, fmaf(q.w, w0.w, px))));
                py = fmaf(q.x, w1.x, fmaf(q.y, w1.y, fmaf(q.z, w1.z, fmaf(q.w, w1.w, py))));
            }
            float u  = (lane & 1) ? py : px;
            float w_ = (lane & 1) ? px : py;
            u += __shfl_xor_sync(0xffffffffu, w_, 1);
            const float pv = __shfl_xor_sync(0xffffffffu, u, 1);
            const int rr = warp * 128 + s * 16 + rrow;
            if (!(lane & 1) && rr + 1 < TT) sv[rr + 1] = make_float2(u, pv);

            __syncwarp();                      // slot consumed before refill
            if (s < CPR - 2)       issue(cur, s + 2, par);          // same row
            else if (nxt)          issue(nxt, s - (CPR - 2), par);  // next row
            asm volatile("cp.async.commit_group;" ::: "memory");    // uniform count
        }
        if (tid == 0)
            sv[0] = make_float2(init_states[2 * b], init_states[2 * b + 1]);
        __syncthreads();                       // sv complete

        // ---------------- Phase B: chunked affine scan ----------------
        float4* svp = reinterpret_cast<float4*>(sv) + tid * 2;

        float2 s2;
        {
            const float4 c0 = svp[0], c1 = svp[1];
            s2 = make_float2(c0.x, c0.y);
            float s1x = fmaf(a00, s2.x, fmaf(a01, s2.y, c0.z));
            float s1y = fmaf(a10, s2.x, fmaf(a11, s2.y, c0.w));
            float s2x = fmaf(a00, s1x, fmaf(a01, s1y, c1.x));
            float s2y = fmaf(a10, s1x, fmaf(a11, s1y, c1.y));
            float s3x = fmaf(a00, s2x, fmaf(a01, s2y, c1.z));
            float s3y = fmaf(a10, s2x, fmaf(a11, s2y, c1.w));
            svp[0] = make_float4(s2.x, s2.y, s1x, s1y);
            svp[1] = make_float4(s2x, s2y, s3x, s3y);
            s2 = make_float2(s3x, s3y);
        }

        float p00 = a00, p01 = a01, p10 = a10, p11 = a11;
        #pragma unroll
        for (int i = 0; i < 2; ++i) {
            float q00 = p00*p00 + p01*p10, q01 = p00*p01 + p01*p11;
            float q10 = p10*p00 + p11*p10, q11 = p10*p01 + p11*p11;
            p00 = q00; p01 = q01; p10 = q10; p11 = q11;
        }

        float2 x = s2;
        #pragma unroll
        for (int d = 0; d < 5; ++d) {
            if (tid == 0) { sPW[d][0]=p00; sPW[d][1]=p01; sPW[d][2]=p10; sPW[d][3]=p11; }
            const int o = 1 << d;
            float ox = __shfl_up_sync(0xffffffffu, x.x, o);
            float oy = __shfl_up_sync(0xffffffffu, x.y, o);
            if (lane >= o) {
                x.x = fmaf(p00, ox, fmaf(p01, oy, x.x));
                x.y = fmaf(p10, ox, fmaf(p11, oy, x.y));
            }
            float q00 = p00*p00 + p01*p10, q01 = p00*p01 + p01*p11;
            float q10 = p10*p00 + p11*p10, q11 = p10*p01 + p11*p11;
            p00 = q00; p01 = q01; p10 = q10; p11 = q11;
        }

        if (lane == 31) agg[warp] = x;
        __syncthreads();

        float2 P = make_float2(0.f, 0.f);
        for (int u = 0; u < warp; ++u) {
            float nx = fmaf(p00, P.x, fmaf(p01, P.y, agg[u].x));
            float ny = fmaf(p10, P.x, fmaf(p11, P.y, agg[u].y));
            P.x = nx; P.y = ny;
        }

        float Ex = __shfl_up_sync(0xffffffffu, x.x, 1);
        float Ey = __shfl_up_sync(0xffffffffu, x.y, 1);
        if (lane == 0) { Ex = 0.f; Ey = 0.f; }

        float m00 = 1.f, m01 = 0.f, m10 = 0.f, m11 = 1.f;
        #pragma unroll
        for (int d = 0; d < 5; ++d) {
            if (lane & (1 << d)) {
                const float v0 = sPW[d][0], v1 = sPW[d][1];
                const float v2 = sPW[d][2], v3 = sPW[d][3];
                float n00 = v0*m00 + v1*m10, n01 = v0*m01 + v1*m11;
                float n10 = v2*m00 + v3*m10, n11 = v2*m01 + v3*m11;
                m00 = n00; m01 = n01; m10 = n10; m11 = n11;
            }
        }
        const float bxp = Ex + m00 * P.x + m01 * P.y;
        const float byp = Ey + m10 * P.x + m11 * P.y;

        float cx = fmaf(a00, bxp, a01 * byp);
        float cy = fmaf(a10, bxp, a11 * byp);
        const float4 r0 = svp[0], r1 = svp[1];
        float4 o0, o1;
        o0.x = r0.x + cx;  o0.y = r0.y + cy;
        { float nx = fmaf(a00, cx, a01 * cy), ny = fmaf(a10, cx, a11 * cy); cx = nx; cy = ny; }
        o0.z = r0.z + cx;  o0.w = r0.w + cy;
        { float nx = fmaf(a00, cx, a01 * cy), ny = fmaf(a10, cx, a11 * cy); cx = nx; cy = ny; }
        o1.x = r1.x + cx;  o1.y = r1.y + cy;
        { float nx = fmaf(a00, cx, a01 * cy), ny = fmaf(a10, cx, a11 * cy); cx = nx; cy = ny; }
        o1.z = r1.z + cx;  o1.w = r1.w + cy;

        float4* op = reinterpret_cast<float4*>(out) + ((size_t)b * TT / 2) + tid * 2;
        __stcs(op,     o0);
        __stcs(op + 1, o1);

        __syncthreads();                      // sv reads done before next row's writes
        cur = nxt;
    }
}

extern "C" void kernel_launch(void* const* d_in, const int* in_sizes, int n_in,
                              void* d_out, int out_size) {
    const float* init_states = (const float*)d_in[0];
    const float* z           = (const float*)d_in[1];
    const float* W           = (const float*)d_in[2];
    float*       out         = (float*)d_out;

    fused_decoder_kernel<<<GRIDX, 256>>>(init_states, z, W, out);
}

// round 10
// speedup vs baseline: 1.0366x; 1.0366x over previous
#include <cuda_runtime.h>
#include <cstdint>

#define BB   2048
#define TT   1024
#define NST  64      // stages per row (16 timesteps each)

__device__ __forceinline__ uint32_t s2u(const void* p) {
    return (uint32_t)__cvta_generic_to_shared(p);
}

// ============================ Fused decoder ================================
// ONE WARP per batch row; 32-thread CTAs; no CTA-wide barriers anywhere.
// z streamed through a private 3-slot cp.async ring (2KB XOR-swizzled chunks,
// 2 chunks always in flight). Each 16-row stage: dot products (2 lanes/row),
// inline 4-level shuffle scan of the affine recurrence, uniform carry update,
// immediate coalesced 128B store. Continuous DRAM demand, zero phase gaps.
__global__ void __launch_bounds__(32)
fused_decoder_kernel(const float* __restrict__ init_states,
                     const float* __restrict__ z,
                     const float* __restrict__ W,
                     float* __restrict__ out) {
    __shared__ alignas(16) float4 ring[3][128];   // 6KB

    const int b      = blockIdx.x;
    const int lane   = threadIdx.x;
    const int parity = lane & 1;
    const int r      = lane >> 1;     // row within stage this lane-pair owns
    const int half   = parity * 4;    // column half of the dot product

    // ---- per-lane weight slice (Wz row0 & row1, columns 16*parity .. +16) ----
    float4 w0[4], w1[4];
    #pragma unroll
    for (int k = 0; k < 4; ++k) {
        const int c = (half + k) * 4;
        w0[k] = make_float4(__ldg(&W[2 + c]),  __ldg(&W[3 + c]),
                            __ldg(&W[4 + c]),  __ldg(&W[5 + c]));
        w1[k] = make_float4(__ldg(&W[36 + c]), __ldg(&W[37 + c]),
                            __ldg(&W[38 + c]), __ldg(&W[39 + c]));
    }

    // ---- swizzled ring offsets (proven R7 pattern) ----
    int woff[4], roff[4];
    #pragma unroll
    for (int k = 0; k < 4; ++k) {
        const int i2 = lane + 32 * k;
        const int row = i2 >> 3, j = i2 & 7;
        woff[k] = row * 8 + ((j + row) & 7);
    }
    #pragma unroll
    for (int k = 0; k < 4; ++k) {
        const int c = half + k;
        roff[k] = r * 8 + ((c + r) & 7);
    }

    // ---- scan constants ----
    const float a00 = __ldg(&W[0]),  a01 = __ldg(&W[1]);
    const float a10 = __ldg(&W[34]), a11 = __ldg(&W[35]);
    float P[5][4];                     // A^(2^d), d = 0..4
    P[0][0] = a00; P[0][1] = a01; P[0][2] = a10; P[0][3] = a11;
    #pragma unroll
    for (int d = 1; d < 5; ++d) {
        const float q00 = P[d-1][0], q01 = P[d-1][1], q10 = P[d-1][2], q11 = P[d-1][3];
        P[d][0] = q00*q00 + q01*q10;  P[d][1] = q00*q01 + q01*q11;
        P[d][2] = q10*q00 + q11*q10;  P[d][3] = q10*q01 + q11*q11;
    }
    // per-lane scan-combine coefficients for levels o = 1,2,4,8
    float pa[4], pb[4];
    #pragma unroll
    for (int d = 0; d < 4; ++d) {
        pa[d] = parity ? P[d][3] : P[d][0];   // multiplies same-component
        pb[d] = parity ? P[d][2] : P[d][1];   // multiplies other-component
    }
    const float a1600 = P[4][0], a1601 = P[4][1], a1610 = P[4][2], a1611 = P[4][3];
    // per-lane row of M = A^(r+1)
    float ma, mb;
    {
        float m00 = 1.f, m01 = 0.f, m10 = 0.f, m11 = 1.f;
        const int e = r + 1;               // 1..16
        #pragma unroll
        for (int d = 0; d < 5; ++d) {
            if (e & (1 << d)) {
                const float n00 = P[d][0]*m00 + P[d][1]*m10;
                const float n01 = P[d][0]*m01 + P[d][1]*m11;
                const float n10 = P[d][2]*m00 + P[d][3]*m10;
                const float n11 = P[d][2]*m01 + P[d][3]*m11;
                m00 = n00; m01 = n01; m10 = n10; m11 = n11;
            }
        }
        ma = parity ? m10 : m00;
        mb = parity ? m11 : m01;
    }

    // ---- carry = init state; store out[b][0] ----
    float cx = __ldg(&init_states[2 * b]);
    float cy = __ldg(&init_states[2 * b + 1]);
    if (lane < 2) out[(size_t)b * 2 * TT + lane] = lane ? cy : cx;

    // ---- prime the 3-slot ring ----
    const float4* zbase = reinterpret_cast<const float4*>(z) + (size_t)b * (TT * 8);
    const uint32_t slotu[3] = { s2u(&ring[0][0]), s2u(&ring[1][0]), s2u(&ring[2][0]) };

    auto issue = [&](int st, int slot) {
        const float4* src = zbase + st * 128 + lane;
        const uint32_t dst = slotu[slot];
        #pragma unroll
        for (int k = 0; k < 4; ++k) {
            asm volatile("cp.async.cg.shared.global [%0], [%1], 16;"
                         :: "r"(dst + (uint32_t)woff[k] * 16u), "l"(src + 32 * k));
        }
    };
    issue(0, 0); asm volatile("cp.async.commit_group;" ::: "memory");
    issue(1, 1); asm volatile("cp.async.commit_group;" ::: "memory");
    issue(2, 2); asm volatile("cp.async.commit_group;" ::: "memory");

    float* orow = out + (size_t)b * 2 * TT + 2 + lane;   // t=16s+r+1 component

    // ======================== main stage loop ========================
    int slot = 0;
    #pragma unroll 1
    for (int s = 0; s < NST; ++s) {
        asm volatile("cp.async.wait_group 2;" ::: "memory");
        __syncwarp();
        const float4* sp = &ring[slot][0];

        // dot products over this lane's column half
        float px = 0.f, py = 0.f;
        #pragma unroll
        for (int k = 0; k < 4; ++k) {
            const float4 q = sp[roff[k]];
            px = fmaf(q.x, w0[k].x, fmaf(q.y, w0[k].y, fmaf(q.z, w0[k].z, fmaf(q.w, w0[k].w, px))));
            py = fmaf(q.x, w1[k].x, fmaf(q.y, w1[k].y, fmaf(q.z, w1[k].z, fmaf(q.w, w1[k].w, py))));
        }
        // pair-reduce: u = this lane's component of v[r]
        float u = (parity ? py : px)
                + __shfl_xor_sync(0xffffffffu, parity ? px : py, 1);

        // 4-level shuffle scan over the 16 rows (component-split lane pairs)
        #pragma unroll
        for (int d = 0; d < 4; ++d) {
            const int o = 1 << d;
            const float same  = __shfl_up_sync(0xffffffffu, u, 2 * o);
            const float other = __shfl_up_sync(0xffffffffu, u, 2 * o - 1 + 2 * parity);
            if (lane >= 2 * o)
                u = fmaf(pa[d], same, fmaf(pb[d], other, u));
        }

        // stage aggregate (row 15) -> all lanes
        const float bx = __shfl_sync(0xffffffffu, u, 30);
        const float by = __shfl_sync(0xffffffffu, u, 31);

        // final state component for t = 16s + r + 1, store (128B coalesced)
        const float ov = u + ma * cx + mb * cy;
        if (s < NST - 1 || lane < 30) __stcs(&orow[32 * s], ov);

        // carry update: c' = agg + A^16 * c
        const float ncx = bx + a1600 * cx + a1601 * cy;
        const float ncy = by + a1610 * cx + a1611 * cy;
        cx = ncx; cy = ncy;

        __syncwarp();                          // slot consumed before refill
        if (s + 3 < NST) issue(s + 3, slot);
        asm volatile("cp.async.commit_group;" ::: "memory");   // uniform count
        slot = (slot == 2) ? 0 : slot + 1;
    }
}

extern "C" void kernel_launch(void* const* d_in, const int* in_sizes, int n_in,
                              void* d_out, int out_size) {
    const float* init_states = (const float*)d_in[0];
    const float* z           = (const float*)d_in[1];
    const float* W           = (const float*)d_in[2];
    float*       out         = (float*)d_out;

    fused_decoder_kernel<<<BB, 32>>>(init_states, z, W, out);
}